// round 2
// baseline (speedup 1.0000x reference)
#include <cuda_runtime.h>
#include <cuda_fp16.h>
#include <cstdint>
#include <cstddef>

// ---------------- problem constants ----------------
#define M_TOT   8192          // B*S = 4*2048
#define N_TOT   4096          // D_OUT
#define K_TOT   4096          // D_IN
#define RANK    16
#define KPAD    4160          // 4096 + 16 (lora) + 48 pad = 65 * 64
#define KCHUNK  64            // halves per chunk = 128 bytes per row
#define NCHUNK  65            // KPAD / KCHUNK
#define CTA_M   128
#define CTA_N   128
#define NSTAGE  4

// scratch (device globals: allocation-free scratch)
__device__ __half g_xh[(size_t)M_TOT * KPAD];   // x (fp16) with lora/pad cols
__device__ __half g_wh[(size_t)N_TOT * KPAD];   // w = q*scale (fp16) with lora/pad cols

// ---------------- helpers ----------------
__device__ __forceinline__ uint32_t smem_u32(const void* p) {
    uint32_t a;
    asm("{ .reg .u64 t; cvta.to.shared.u64 t, %1; cvt.u32.u64 %0, t; }" : "=r"(a) : "l"(p));
    return a;
}
__device__ __forceinline__ void cp16(uint32_t smem_dst, const void* gmem_src) {
    asm volatile("cp.async.cg.shared.global [%0], [%1], 16;" :: "r"(smem_dst), "l"(gmem_src) : "memory");
}
__device__ __forceinline__ uint32_t sw128(uint32_t off) { return off ^ ((off >> 3) & 0x70); }

#define LDMX4(r, addr) \
    asm volatile("ldmatrix.sync.aligned.m8n8.x4.shared.b16 {%0,%1,%2,%3}, [%4];" \
        : "=r"((r)[0]), "=r"((r)[1]), "=r"((r)[2]), "=r"((r)[3]) : "r"(addr))

#define MMA16816(c, a, b) \
    asm volatile("mma.sync.aligned.m16n8k16.row.col.f32.f16.f16.f32 " \
        "{%0,%1,%2,%3}, {%4,%5,%6,%7}, {%8,%9}, {%0,%1,%2,%3};" \
        : "+f"((c)[0]), "+f"((c)[1]), "+f"((c)[2]), "+f"((c)[3]) \
        : "r"((a)[0]), "r"((a)[1]), "r"((a)[2]), "r"((a)[3]), "r"((b)[0]), "r"((b)[1]))

// ---------------- pre-pass kernels ----------------

// x fp32 -> g_xh fp16 for k<4096; zero for k>=4096 (lora cols written later by k_xa)
__global__ void k_convert_x(const float* __restrict__ x) {
    size_t id = (size_t)blockIdx.x * blockDim.x + threadIdx.x;
    const size_t total = (size_t)M_TOT * (KPAD / 8);
    if (id >= total) return;
    int m = (int)(id / (KPAD / 8));
    int c = (int)(id % (KPAD / 8));
    __align__(16) __half h[8];
    if (c < K_TOT / 8) {
        const float4* p = (const float4*)(x + (size_t)m * K_TOT + (size_t)c * 8);
        float4 a = p[0], b = p[1];
        h[0] = __float2half_rn(a.x); h[1] = __float2half_rn(a.y);
        h[2] = __float2half_rn(a.z); h[3] = __float2half_rn(a.w);
        h[4] = __float2half_rn(b.x); h[5] = __float2half_rn(b.y);
        h[6] = __float2half_rn(b.z); h[7] = __float2half_rn(b.w);
    } else {
        #pragma unroll
        for (int j = 0; j < 8; j++) h[j] = __half(0.0f);
    }
    *(uint4*)(g_xh + (size_t)m * KPAD + (size_t)c * 8) = *(uint4*)h;
}

// qweight int32 -> g_wh fp16 (q * scale); cols 4096..4111 = lora_B[r][n]; rest zero
__global__ void k_convert_w(const int* __restrict__ qw, const float* __restrict__ scales,
                            const float* __restrict__ lB) {
    size_t id = (size_t)blockIdx.x * blockDim.x + threadIdx.x;
    const size_t total = (size_t)N_TOT * (KPAD / 8);
    if (id >= total) return;
    int n = (int)(id / (KPAD / 8));
    int c = (int)(id % (KPAD / 8));
    __align__(16) __half h[8];
    if (c < K_TOT / 8) {
        float s = __ldg(scales);
        const int4* p = (const int4*)(qw + (size_t)n * K_TOT + (size_t)c * 8);
        int4 a = p[0], b = p[1];
        h[0] = __float2half_rn((float)a.x * s); h[1] = __float2half_rn((float)a.y * s);
        h[2] = __float2half_rn((float)a.z * s); h[3] = __float2half_rn((float)a.w * s);
        h[4] = __float2half_rn((float)b.x * s); h[5] = __float2half_rn((float)b.y * s);
        h[6] = __float2half_rn((float)b.z * s); h[7] = __float2half_rn((float)b.w * s);
    } else if (c == K_TOT / 8 || c == K_TOT / 8 + 1) {
        int rbase = (c - K_TOT / 8) * 8;
        #pragma unroll
        for (int j = 0; j < 8; j++)
            h[j] = __float2half_rn(__ldg(lB + (size_t)(rbase + j) * N_TOT + n)); // SCALING = 1
    } else {
        #pragma unroll
        for (int j = 0; j < 8; j++) h[j] = __half(0.0f);
    }
    *(uint4*)(g_wh + (size_t)n * KPAD + (size_t)c * 8) = *(uint4*)h;
}

// xA[m, r] = sum_k x[m,k] * A[k,r]  -> g_xh[m, 4096+r]  (fp16)
__global__ void k_xa(const float* __restrict__ x, const float* __restrict__ A) {
    __shared__ float xs[64][65];
    int t = threadIdx.x;
    int m0 = blockIdx.x * 64;
    int ml = t & 63, rg = t >> 6;
    float a0 = 0.f, a1 = 0.f, a2 = 0.f, a3 = 0.f;
    for (int kc = 0; kc < K_TOT; kc += 64) {
        #pragma unroll
        for (int j = 0; j < 4; j++) {
            int idx = t * 4 + j;
            int row = idx >> 4;
            int c4  = (idx & 15) * 4;
            float4 v = *(const float4*)(x + (size_t)(m0 + row) * K_TOT + kc + c4);
            xs[row][c4] = v.x; xs[row][c4 + 1] = v.y; xs[row][c4 + 2] = v.z; xs[row][c4 + 3] = v.w;
        }
        __syncthreads();
        #pragma unroll 8
        for (int k = 0; k < 64; k++) {
            float xv = xs[ml][k];
            float4 av = __ldg((const float4*)(A + (size_t)(kc + k) * RANK + rg * 4));
            a0 += xv * av.x; a1 += xv * av.y; a2 += xv * av.z; a3 += xv * av.w;
        }
        __syncthreads();
    }
    __half* dst = g_xh + (size_t)(m0 + ml) * KPAD + K_TOT + rg * 4;
    dst[0] = __float2half_rn(a0); dst[1] = __float2half_rn(a1);
    dst[2] = __float2half_rn(a2); dst[3] = __float2half_rn(a3);
}

// ---------------- main GEMM (mma.sync HMMA, 4-stage cp.async pipeline) ----------------
// smem: A stages [0, NSTAGE*16KB), B stages [NSTAGE*16KB, 2*NSTAGE*16KB)
// each stage: 128 rows x 128 bytes, SW128-swizzled
#define STAGE_BYTES 16384
#define SMEM_BYTES  (2 * NSTAGE * STAGE_BYTES)

__global__ void __launch_bounds__(256)
k_gemm(const float* __restrict__ bias, float* __restrict__ out) {
    extern __shared__ char smem[];
    const uint32_t sb = smem_u32(smem);
    const int tid  = threadIdx.x;
    const int wid  = tid >> 5;
    const int lane = tid & 31;
    const int n0 = blockIdx.x * CTA_N;
    const int m0 = blockIdx.y * CTA_M;

    const int wm = wid & 1;        // 0..1 -> m offset wm*64
    const int wn = wid >> 1;       // 0..3 -> n offset wn*32

    // per-thread ldmatrix base offsets (relative to stage base, pre-swizzle)
    // A (x4, non-trans): lanes 0-15 -> rows (lane&15) @k+0 ; lanes 16-31 -> rows @k+16
    const uint32_t a_rel = (uint32_t)(wm * 64 + (lane & 15)) * 128 + ((lane >> 4) * 16);
    // B (x4, non-trans): lanes {0-7,8-15,16-23,24-31} -> rows +0 k0 / +0 k16 / +8 k0 / +8 k16
    const uint32_t b_rel = (uint32_t)(wn * 32 + (lane & 7) + ((lane >> 4) << 3)) * 128
                         + (((lane >> 3) & 1) * 16);

    auto load_stage = [&](int s, int kc) {
        const uint32_t saA = sb + s * STAGE_BYTES;
        const uint32_t saB = sb + NSTAGE * STAGE_BYTES + s * STAGE_BYTES;
        #pragma unroll
        for (int i = 0; i < 4; i++) {
            int idx = tid + 256 * i;            // 0..1023
            int row = idx >> 3, c = idx & 7;
            uint32_t off = (uint32_t)row * 128 + c * 16;
            const char* gA = (const char*)(g_xh + (size_t)(m0 + row) * KPAD) + kc * 128 + c * 16;
            const char* gB = (const char*)(g_wh + (size_t)(n0 + row) * KPAD) + kc * 128 + c * 16;
            cp16(saA + sw128(off), gA);
            cp16(saB + sw128(off), gB);
        }
    };

    float acc[4][4][4];
    #pragma unroll
    for (int i = 0; i < 4; i++)
        #pragma unroll
        for (int j = 0; j < 4; j++)
            #pragma unroll
            for (int r = 0; r < 4; r++) acc[i][j][r] = 0.f;

    // prologue: fill NSTAGE-1 stages
    #pragma unroll
    for (int s = 0; s < NSTAGE - 1; s++) {
        load_stage(s, s);
        asm volatile("cp.async.commit_group;" ::: "memory");
    }

    for (int kc = 0; kc < NCHUNK; kc++) {
        asm volatile("cp.async.wait_group %0;" :: "n"(NSTAGE - 2) : "memory");
        __syncthreads();

        const int s = kc & (NSTAGE - 1);
        const uint32_t stA = sb + s * STAGE_BYTES;
        const uint32_t stB = sb + NSTAGE * STAGE_BYTES + s * STAGE_BYTES;

        #pragma unroll
        for (int ks = 0; ks < 4; ks++) {        // 4 x k16 per 64-chunk
            uint32_t a[4][4];
            #pragma unroll
            for (int mt = 0; mt < 4; mt++)
                LDMX4(a[mt], stA + sw128(a_rel + (uint32_t)mt * 2048 + ks * 32));
            uint32_t b[2][4];                   // b[p][0..1]=ntile 2p, [2..3]=ntile 2p+1
            #pragma unroll
            for (int p = 0; p < 2; p++)
                LDMX4(b[p], stB + sw128(b_rel + (uint32_t)p * 2048 + ks * 32));
            #pragma unroll
            for (int mt = 0; mt < 4; mt++)
                #pragma unroll
                for (int nt = 0; nt < 4; nt++)
                    MMA16816(acc[mt][nt], a[mt], &b[nt >> 1][(nt & 1) * 2]);
        }

        __syncthreads();
        const int lkc = kc + NSTAGE - 1;
        if (lkc < NCHUNK) load_stage(lkc & (NSTAGE - 1), lkc);
        asm volatile("cp.async.commit_group;" ::: "memory");
    }

    // -------- epilogue: acc + bias -> out (fp32) --------
    #pragma unroll
    for (int mt = 0; mt < 4; mt++) {
        const int m = m0 + wm * 64 + mt * 16 + (lane >> 2);
        #pragma unroll
        for (int nt = 0; nt < 4; nt++) {
            const int n = n0 + wn * 32 + nt * 8 + (lane & 3) * 2;
            float2 bv = __ldg((const float2*)(bias + n));
            float2 v0 = make_float2(acc[mt][nt][0] + bv.x, acc[mt][nt][1] + bv.y);
            float2 v1 = make_float2(acc[mt][nt][2] + bv.x, acc[mt][nt][3] + bv.y);
            *(float2*)(out + (size_t)m * N_TOT + n)       = v0;
            *(float2*)(out + (size_t)(m + 8) * N_TOT + n) = v1;
        }
    }
}

// ---------------- launch ----------------
extern "C" void kernel_launch(void* const* d_in, const int* in_sizes, int n_in,
                              void* d_out, int out_size) {
    (void)in_sizes; (void)n_in; (void)out_size;
    const float* x      = (const float*)d_in[0];
    const int*   qw     = (const int*)d_in[1];
    const float* scales = (const float*)d_in[2];
    const float* bias   = (const float*)d_in[3];
    const float* lA     = (const float*)d_in[4];
    const float* lB     = (const float*)d_in[5];
    float* out = (float*)d_out;

    cudaFuncSetAttribute(k_gemm, cudaFuncAttributeMaxDynamicSharedMemorySize, SMEM_BYTES);

    {   // x convert (+ zero pad cols)
        size_t total = (size_t)M_TOT * (KPAD / 8);
        k_convert_x<<<(unsigned)((total + 255) / 256), 256>>>(x);
    }
    {   // w convert (+ lora_B cols + zero pad)
        size_t total = (size_t)N_TOT * (KPAD / 8);
        k_convert_w<<<(unsigned)((total + 255) / 256), 256>>>(qw, scales, lB);
    }
    // x @ lora_A -> g_xh lora columns (after convert_x zeroed them)
    k_xa<<<M_TOT / 64, 256>>>(x, lA);

    dim3 grid(N_TOT / CTA_N, M_TOT / CTA_M);
    k_gemm<<<grid, 256, SMEM_BYTES>>>(bias, out);
}